// round 11
// baseline (speedup 1.0000x reference)
#include <cuda_runtime.h>
#include <cuda_bf16.h>
#include <math.h>
#include <stdint.h>

#define NTOK 1024
#define NEXP 16
#define HDIM 1024
#define DDIM 2048
#define RDIM 16
#define NP   2048          // (token, k) pairs
#define UPW  2048          // 2*H
#define SCALE 0.25f

// -------- device scratch: referenced ONLY from device code (GB300/ATS host-shadow trap) --
__device__ int   g_setupdone;
__device__ int   g_bindfail;
__device__ int   g_ids[NP];
__device__ float g_tw[NP];
__device__ int   g_off[NEXP + 1];
__device__ int   g_pairs[NP];
__device__ float g_t[NP * RDIM];
__device__ float g_t2[NP * RDIM];
__device__ __align__(16) float g_up[(size_t)NP * UPW];
__device__ __align__(16) float g_act[(size_t)NP * HDIM];
__device__ __align__(16) float g_down[(size_t)NP * DDIM];

__device__ __forceinline__ unsigned f2tf(float f) {
    unsigned u;
    asm("cvt.rna.tf32.f32 %0, %1;" : "=r"(u) : "f"(f));
    return u;
}
__device__ __forceinline__ unsigned u2tf(unsigned x) { return f2tf(__uint_as_float(x)); }
__device__ __forceinline__ uint32_t smem_u32(const void* p) {
    uint32_t a;
    asm("{ .reg .u64 t; cvta.to.shared.u64 t, %1; cvt.u32.u64 %0, t; }" : "=r"(a) : "l"(p));
    return a;
}
#define CP_COMMIT() asm volatile("cp.async.commit_group;" ::: "memory")
#define CP_WAIT1()  asm volatile("cp.async.wait_group 1;" ::: "memory")
#define CP_WAIT0()  asm volatile("cp.async.wait_group 0;" ::: "memory")

// -------- setup: semantic id/weight identification + expert grouping --------
__global__ __launch_bounds__(256) void setup_kernel(const unsigned* __restrict__ cA,
                                                    const unsigned* __restrict__ cB) {
    __shared__ int wf32[2];
    __shared__ int idu[2], idl[2], idf[2];
    __shared__ int cnt[NEXP], cur[NEXP];
    __shared__ int idsc, idsmode;
    int tid = threadIdx.x;
    if (tid < 2) { wf32[tid] = 0; idu[tid] = 0; idl[tid] = 0; idf[tid] = 0; }
    if (tid < NEXP) cnt[tid] = 0;
    __syncthreads();

    for (int c = 0; c < 2; c++) {
        const unsigned* X = c ? cB : cA;
        int sf = 0, bu = 0, bl = 0, bf = 0;
        for (int t = tid; t < 512; t += 256) {
            unsigned w0 = X[2 * t], w1 = X[2 * t + 1];
            float a = __uint_as_float(w0), b = __uint_as_float(w1);
            if (fabsf(a + b - 1.0f) < 0.02f) sf++;
            if (w0 >= NEXP || w1 >= NEXP) bu = 1;
            if (w0 >= NEXP || w1 != 0) bl = 1;
            if (!(a >= 0.f && a < (float)NEXP && a == floorf(a)) ||
                !(b >= 0.f && b < (float)NEXP && b == floorf(b))) bf = 1;
        }
        atomicAdd(&wf32[c], sf);
        if (bu) atomicExch(&idu[c], 1);
        if (bl) atomicExch(&idl[c], 1);
        if (bf) atomicExch(&idf[c], 1);
    }
    __syncthreads();

    if (tid == 0) {
        int wmode[2], imode[2];
        for (int c = 0; c < 2; c++) {
            wmode[c] = (wf32[c] > 480) ? 1 : 0;
            imode[c] = (!idl[c]) ? 2 : ((!idu[c]) ? 1 : ((!idf[c]) ? 3 : 0));
        }
        int ic = -1;
        if (imode[0] && wmode[1]) ic = 0;
        else if (imode[1] && wmode[0]) ic = 1;
        g_bindfail = (ic < 0) ? 1 : 0;
        idsc = (ic < 0) ? 0 : ic;
        idsmode = imode[idsc] ? imode[idsc] : 1;
    }
    __syncthreads();

    const unsigned* idsbuf = idsc ? cB : cA;
    const unsigned* twbuf  = idsc ? cA : cB;
    int im = idsmode;
    for (int p = tid; p < NP; p += 256) {
        int id;
        if (im == 2)      id = (int)idsbuf[2 * p];
        else if (im == 3) id = (int)__uint_as_float(idsbuf[p]);
        else              id = (int)idsbuf[p];
        g_ids[p] = id & (NEXP - 1);
        g_tw[p] = __uint_as_float(twbuf[p]);
    }
    __syncthreads();

    for (int p = tid; p < NP; p += 256) atomicAdd(&cnt[g_ids[p]], 1);
    __syncthreads();
    if (tid == 0) {
        int a = 0;
        for (int e = 0; e < NEXP; e++) { g_off[e] = a; a += cnt[e]; }
        g_off[NEXP] = a;
    }
    __syncthreads();
    if (tid < NEXP) cur[tid] = g_off[tid];
    __syncthreads();
    for (int p = tid; p < NP; p += 256) {
        int pos = atomicAdd(&cur[g_ids[p]], 1);
        g_pairs[pos & (NP - 1)] = p;
    }
    __syncthreads();
    if (tid == 0) g_setupdone = 1;
}

// -------- seeds (diagnostic sentinels) --------
__global__ __launch_bounds__(256) void seed_kernel(float* __restrict__ outv) {
    int i = blockIdx.x * blockDim.x + threadIdx.x;
    if (i == 0) { g_t[0] = 777.0f; g_t2[0] = 777.0f; }
    if (i < 256) { g_up[i] = 12345.0f; g_down[i] = 0.125f; }
    if (i < NTOK * DDIM) outv[i] = 0.5f;
}

// -------- LoRA-A GEMV (fp32) --------
template <bool DOWN>
__global__ __launch_bounds__(256) void lora_t_kernel(const float* __restrict__ Xv,
                                                     const float* __restrict__ A, int Dlen) {
    int p = blockIdx.x;
    int e = g_ids[p];
    float* T = DOWN ? g_t2 : g_t;
    int warp = threadIdx.x >> 5, lane = threadIdx.x & 31;
    const float* xrow = DOWN ? (g_act + (size_t)p * Dlen)
                             : (Xv + (size_t)(p >> 1) * Dlen);
    for (int r = warp; r < RDIM; r += 8) {
        const float* a = A + ((size_t)e * RDIM + r) * Dlen;
        float s = 0.f;
        for (int i = lane * 4; i < Dlen; i += 128) {
            float4 xv = *(const float4*)(xrow + i);
            float4 av = *(const float4*)(a + i);
            s += xv.x * av.x + xv.y * av.y + xv.z * av.z + xv.w * av.w;
        }
        #pragma unroll
        for (int o = 16; o; o >>= 1) s += __shfl_xor_sync(0xffffffffu, s, o);
        if (lane == 0) T[p * RDIM + r] = s;
    }
}

// ======= expert-grouped tf32 GEMM: 128x256x32 tile, 64x64 warp tile, 3-stage cp.async ======
// 8 warps = 2(M) x 4(N). Smem word(r,k) = r*32 + ((k>>2 ^ r%8)<<2) + k%4.
#define BM 128
#define BN 256
#define BK 32
#define STWA (BM * 32)
#define STWB (BN * 32)
#define PIPE_SMEM (3 * (STWA + STWB) * 4 + 512)

__device__ __forceinline__ void stsw(unsigned* tile, int r, int kb, float4 v) {
    int idx = r * 32 + ((((kb >> 2) ^ (r & 7)) << 2));
    uint4 u = make_uint4(f2tf(v.x), f2tf(v.y), f2tf(v.z), f2tf(v.w));
    *(uint4*)&tile[idx] = u;
}
__device__ __forceinline__ unsigned ldsw(const unsigned* tile, int r, int k) {
    return tile[r * 32 + (((k >> 2) ^ (r & 7)) << 2) + (k & 3)];
}
__device__ __forceinline__ void cp16(uint32_t dst, const float* src) {
    asm volatile("cp.async.cg.shared.global [%0], [%1], 16;" :: "r"(dst), "l"(src));
}
// A: thread owns row tid>>1, k-half (tid&1)*16 (4 cp16). B: thread owns row tid, full 32k (8 cp16).
__device__ __forceinline__ void issue_chunk(uint32_t a_s, uint32_t b_s,
                                            const float* ap, const float* bp, int tid) {
    int lrow = tid >> 1, kh4 = (tid & 1) * 4;
    int rxa = lrow & 7;
    #pragma unroll
    for (int j = 0; j < 4; j++) {
        uint32_t off = (uint32_t)(lrow * 32 + (((kh4 + j) ^ rxa) << 2)) * 4u;
        cp16(a_s + off, ap + j * 4);
    }
    int rxb = tid & 7;
    #pragma unroll
    for (int j = 0; j < 8; j++) {
        uint32_t off = (uint32_t)(tid * 32 + ((j ^ rxb) << 2)) * 4u;
        cp16(b_s + off, bp + j * 4);
    }
}
// MMA sweep: warp tile 64(M) x 64(N), mt=4, nt=8
__device__ __forceinline__ void frag_mma(const unsigned* As, const unsigned* Bs,
                                         int am_base, int bn_base, int kl, int rquad,
                                         int nks, float c[4][8][4]) {
    for (int ks = 0; ks < nks; ks++) {
        int k0 = ks * 8 + kl;
        unsigned a0[4], a1[4], a2[4], a3[4];
        #pragma unroll
        for (int mt = 0; mt < 4; mt++) {
            int r0 = am_base + mt * 16 + rquad;
            a0[mt] = u2tf(ldsw(As, r0, k0));
            a1[mt] = u2tf(ldsw(As, r0 + 8, k0));
            a2[mt] = u2tf(ldsw(As, r0, k0 + 4));
            a3[mt] = u2tf(ldsw(As, r0 + 8, k0 + 4));
        }
        #pragma unroll
        for (int nt = 0; nt < 8; nt++) {
            int cn = bn_base + nt * 8 + rquad;
            unsigned b0 = u2tf(ldsw(Bs, cn, k0));
            unsigned b1 = u2tf(ldsw(Bs, cn, k0 + 4));
            #pragma unroll
            for (int mt = 0; mt < 4; mt++) {
                asm volatile(
                    "mma.sync.aligned.m16n8k8.row.col.f32.tf32.tf32.f32 "
                    "{%0,%1,%2,%3}, {%4,%5,%6,%7}, {%8,%9}, {%0,%1,%2,%3};"
                    : "+f"(c[mt][nt][0]), "+f"(c[mt][nt][1]),
                      "+f"(c[mt][nt][2]), "+f"(c[mt][nt][3])
                    : "r"(a0[mt]), "r"(a1[mt]), "r"(a2[mt]), "r"(a3[mt]),
                      "r"(b0), "r"(b1));
            }
        }
    }
}

template <bool IS_DOWN>
__global__ __launch_bounds__(256) void mma_gemm(const float* __restrict__ Av,   // hidden (up only)
                                                const float* __restrict__ W,    // [E, Ncols, Kd]
                                                const float* __restrict__ LB,   // [E, Ncols, R]
                                                int Kd, int Ncols) {
    int e = blockIdx.z;
    int mstart = g_off[e] + blockIdx.y * BM;
    int mend = g_off[e + 1];
    if (mstart >= mend) return;
    int mv = min(BM, mend - mstart);
    int o0 = blockIdx.x * BN;

    extern __shared__ __align__(16) unsigned dynsmem[];
    unsigned* Abuf = dynsmem;                    // 3 stages x STWA
    unsigned* Bbuf = dynsmem + 3 * STWA;         // 3 stages x STWB
    int* Pr = (int*)(dynsmem + 3 * (STWA + STWB));

    int tid = threadIdx.x;
    int lane = tid & 31, wid = tid >> 5;
    int am_base = (wid >> 2) * 64;
    int bn_base = (wid & 3) * 64;

    if (tid < BM) Pr[tid] = g_pairs[mstart + ((tid < mv) ? tid : (mv - 1))];
    __syncthreads();

    int lrow = tid >> 1, khalf = (tid & 1) * 16;
    int prow = Pr[lrow];
    int arow = IS_DOWN ? prow : (prow >> 1);
    const float* abase = (IS_DOWN ? g_act : Av) + (size_t)arow * Kd + khalf;
    const float* bbase = W + ((size_t)e * Ncols + o0 + tid) * Kd;

    uint32_t a_s0 = smem_u32(Abuf), b_s0 = smem_u32(Bbuf);

    float c[4][8][4];
    #pragma unroll
    for (int i = 0; i < 4; i++)
        #pragma unroll
        for (int j = 0; j < 8; j++)
            #pragma unroll
            for (int q = 0; q < 4; q++) c[i][j][q] = 0.f;

    int nch = Kd / BK;
    int kl = (lane & 3);
    int rquad = lane >> 2;

    // prologue: stage chunks 0,1
    issue_chunk(a_s0, b_s0, abase, bbase, tid);
    CP_COMMIT();
    if (nch > 1) issue_chunk(a_s0 + STWA * 4, b_s0 + STWB * 4, abase + BK, bbase + BK, tid);
    CP_COMMIT();

    for (int ch = 0; ch < nch; ch++) {
        CP_WAIT1();
        __syncthreads();
        int nx = ch + 2;
        if (nx < nch) {
            int st = nx - (nx / 3) * 3;
            issue_chunk(a_s0 + st * STWA * 4, b_s0 + st * STWB * 4,
                        abase + nx * BK, bbase + nx * BK, tid);
        }
        CP_COMMIT();
        int st = ch - (ch / 3) * 3;
        frag_mma(Abuf + st * STWA, Bbuf + st * STWB, am_base, bn_base, kl, rquad, 4, c);
    }

    // ---- LoRA-B extension chunk (K=16): A <- SCALE*T[p][r], B <- LB[n][r] ----
    CP_WAIT0();
    __syncthreads();
    if (tid < BM) {
        const float* tp = (IS_DOWN ? g_t2 : g_t) + Pr[tid] * RDIM;
        #pragma unroll
        for (int j = 0; j < 4; j++) {
            float4 v = *(const float4*)(tp + j * 4);
            v.x *= SCALE; v.y *= SCALE; v.z *= SCALE; v.w *= SCALE;
            stsw(Abuf, tid, j * 4, v);
        }
    }
    {
        const float* lp = LB + ((size_t)e * Ncols + o0 + tid) * RDIM;
        #pragma unroll
        for (int j = 0; j < 4; j++)
            stsw(Bbuf, tid, j * 4, *(const float4*)(lp + j * 4));
    }
    __syncthreads();
    frag_mma(Abuf, Bbuf, am_base, bn_base, kl, rquad, 2, c);

    // ---- writeout ----
    float* Out = IS_DOWN ? g_down : g_up;
    #pragma unroll
    for (int mt = 0; mt < 4; mt++) {
        int m0 = am_base + mt * 16 + rquad;
        #pragma unroll
        for (int half = 0; half < 2; half++) {
            int m = m0 + half * 8;
            if (m >= mv) continue;
            int p = Pr[m];
            float w = IS_DOWN ? g_tw[p] : 1.0f;
            float* op = Out + (size_t)p * Ncols + o0;
            #pragma unroll
            for (int nt = 0; nt < 8; nt++) {
                int n = bn_base + nt * 8 + (lane & 3) * 2;
                float2 v;
                v.x = c[mt][nt][half * 2 + 0];
                v.y = c[mt][nt][half * 2 + 1];
                if (IS_DOWN) { v.x *= w; v.y *= w; }
                *(float2*)&op[n] = v;
            }
        }
    }
}

// -------- gelu(up[:H]) * up[H:] --------
__global__ __launch_bounds__(256) void act_kernel() {
    int i = blockIdx.x * blockDim.x + threadIdx.x;
    if (i >= NP * HDIM) return;
    int p = i >> 10, h = i & (HDIM - 1);
    float a = g_up[(size_t)p * UPW + h];
    float b = g_up[(size_t)p * UPW + HDIM + h];
    float ge = 0.5f * a * (1.0f + erff(a * 0.70710678118654752f));
    g_act[(size_t)p * HDIM + h] = ge * b;
}

// -------- combine + verdict --------
__global__ __launch_bounds__(256) void combine_verdict(float* __restrict__ outv) {
    int code = 0;
    if (!g_setupdone)               code = 1;
    else if (g_bindfail)            code = 2;
    else if (g_off[NEXP] != NP)     code = 4;
    else if (g_t[0] == 777.0f)      code = 3;
    else if (g_up[0] == 12345.0f)   code = 8;
    else if (g_t2[0] == 777.0f)     code = 5;
    else if (g_down[0] == 0.125f)   code = 16;
    int i = blockIdx.x * blockDim.x + threadIdx.x;
    if (i >= NTOK * DDIM) return;
    float v;
    if (code) v = (float)code;
    else {
        int n = i >> 11, d = i & (DDIM - 1);
        v = g_down[(size_t)(2 * n) * DDIM + d] + g_down[(size_t)(2 * n + 1) * DDIM + d];
    }
    outv[i] = v;
}

extern "C" void kernel_launch(void* const* d_in, const int* in_sizes, int n_in,
                              void* d_out, int out_size) {
    long long mx = 0;
    for (int i = 0; i < n_in; i++) if ((long long)in_sizes[i] > mx) mx = in_sizes[i];
    int div = 1;
    if (mx == 268435456LL) div = 4;
    else if (mx == 134217728LL) div = 2;

    int idx_hidden = -1, idx_wup = -1, idx_wdown = -1, idx_downa = -1;
    int idxc[2] = {-1, -1}; int nc = 0;
    int idx512k[3] = {-1, -1, -1}; int n512k = 0;
    for (int i = 0; i < n_in; i++) {
        long long es = (long long)in_sizes[i] / div;
        if      (es == 2097152)  idx_hidden = i;
        else if (es == 67108864) idx_wup = i;
        else if (es == 33554432) idx_wdown = i;
        else if (es == 262144)   idx_downa = i;
        else if (es == 2048 || (div == 2 && es == 4096)) { if (nc < 2) idxc[nc++] = i; }
        else if (es == 524288)   { if (n512k < 3) idx512k[n512k++] = i; }
    }

    int idx_upa = -1, idx_upb = -1, idx_downb = -1;
    bool ok = (idx_hidden >= 0 && idx_wup >= 0 && idx_wdown >= 0 && idx_downa >= 0 &&
               nc == 2 && n512k == 3);
    if (ok) {
        if (idx_downa < idx512k[0]) { idx_downb = idx512k[0]; idx_upa = idx512k[1]; idx_upb = idx512k[2]; }
        else                        { idx_upa = idx512k[0]; idx_upb = idx512k[1]; idx_downb = idx512k[2]; }
    } else if (n_in >= 9) {
        idx_hidden = 0; idxc[0] = 1; idxc[1] = 2; idx_wup = 3; idx_wdown = 4;
        idx_upa = 5; idx_upb = 6; idx_downa = 7; idx_downb = 8;
    } else {
        return;
    }

    const float* hidden = (const float*)d_in[idx_hidden];
    const float* w_up   = (const float*)d_in[idx_wup];
    const float* w_down = (const float*)d_in[idx_wdown];
    const float* up_a   = (const float*)d_in[idx_upa];
    const float* up_b   = (const float*)d_in[idx_upb];
    const float* down_a = (const float*)d_in[idx_downa];
    const float* down_b = (const float*)d_in[idx_downb];
    float* out = (float*)d_out;

    static int smem_set = 0;
    if (!smem_set) {
        cudaFuncSetAttribute(mma_gemm<false>, cudaFuncAttributeMaxDynamicSharedMemorySize, PIPE_SMEM);
        cudaFuncSetAttribute(mma_gemm<true>,  cudaFuncAttributeMaxDynamicSharedMemorySize, PIPE_SMEM);
        smem_set = 1;
    }

    setup_kernel<<<1, 256>>>((const unsigned*)d_in[idxc[0]], (const unsigned*)d_in[idxc[1]]);
    seed_kernel<<<(NTOK * DDIM + 255) / 256, 256>>>(out);

    lora_t_kernel<false><<<NP, 256>>>(hidden, up_a, DDIM);

    {
        dim3 grid(UPW / BN, (NP + BM - 1) / BM, NEXP);
        mma_gemm<false><<<grid, 256, PIPE_SMEM>>>(hidden, w_up, up_b, DDIM, UPW);
    }

    act_kernel<<<(NP * HDIM + 255) / 256, 256>>>();

    lora_t_kernel<true><<<NP, 256>>>(nullptr, down_a, HDIM);

    {
        dim3 grid(DDIM / BN, (NP + BM - 1) / BM, NEXP);
        mma_gemm<true><<<grid, 256, PIPE_SMEM>>>(nullptr, w_down, down_b, HDIM, DDIM);
    }

    combine_verdict<<<(NTOK * DDIM + 255) / 256, 256>>>(out);
}

// round 12
// speedup vs baseline: 1.4266x; 1.4266x over previous
#include <cuda_runtime.h>
#include <cuda_bf16.h>
#include <math.h>
#include <stdint.h>

#define NTOK 1024
#define NEXP 16
#define HDIM 1024
#define DDIM 2048
#define RDIM 16
#define NP   2048          // (token, k) pairs
#define UPW  2048          // 2*H
#define SCALE 0.25f

// -------- device scratch: referenced ONLY from device code (GB300/ATS host-shadow trap) --
__device__ int   g_setupdone;
__device__ int   g_bindfail;
__device__ int   g_ids[NP];
__device__ float g_tw[NP];
__device__ int   g_off[NEXP + 1];
__device__ int   g_pairs[NP];
__device__ float g_t[NP * RDIM];
__device__ float g_t2[NP * RDIM];
__device__ __align__(16) float g_up[(size_t)NP * UPW];
__device__ __align__(16) float g_act[(size_t)NP * HDIM];

__device__ __forceinline__ unsigned f2tf(float f) {   // used only in LoRA store path
    unsigned u;
    asm("cvt.rna.tf32.f32 %0, %1;" : "=r"(u) : "f"(f));
    return u;
}
__device__ __forceinline__ uint32_t smem_u32(const void* p) {
    uint32_t a;
    asm("{ .reg .u64 t; cvta.to.shared.u64 t, %1; cvt.u32.u64 %0, t; }" : "=r"(a) : "l"(p));
    return a;
}
#define CP_COMMIT() asm volatile("cp.async.commit_group;" ::: "memory")
#define CP_WAIT1()  asm volatile("cp.async.wait_group 1;" ::: "memory")
#define CP_WAIT0()  asm volatile("cp.async.wait_group 0;" ::: "memory")

// -------- setup: semantic id/weight identification + expert grouping --------
__global__ __launch_bounds__(256) void setup_kernel(const unsigned* __restrict__ cA,
                                                    const unsigned* __restrict__ cB) {
    __shared__ int wf32[2];
    __shared__ int idu[2], idl[2], idf[2];
    __shared__ int cnt[NEXP], cur[NEXP];
    __shared__ int idsc, idsmode;
    int tid = threadIdx.x;
    if (tid < 2) { wf32[tid] = 0; idu[tid] = 0; idl[tid] = 0; idf[tid] = 0; }
    if (tid < NEXP) cnt[tid] = 0;
    __syncthreads();

    for (int c = 0; c < 2; c++) {
        const unsigned* X = c ? cB : cA;
        int sf = 0, bu = 0, bl = 0, bf = 0;
        for (int t = tid; t < 512; t += 256) {
            unsigned w0 = X[2 * t], w1 = X[2 * t + 1];
            float a = __uint_as_float(w0), b = __uint_as_float(w1);
            if (fabsf(a + b - 1.0f) < 0.02f) sf++;
            if (w0 >= NEXP || w1 >= NEXP) bu = 1;
            if (w0 >= NEXP || w1 != 0) bl = 1;
            if (!(a >= 0.f && a < (float)NEXP && a == floorf(a)) ||
                !(b >= 0.f && b < (float)NEXP && b == floorf(b))) bf = 1;
        }
        atomicAdd(&wf32[c], sf);
        if (bu) atomicExch(&idu[c], 1);
        if (bl) atomicExch(&idl[c], 1);
        if (bf) atomicExch(&idf[c], 1);
    }
    __syncthreads();

    if (tid == 0) {
        int wmode[2], imode[2];
        for (int c = 0; c < 2; c++) {
            wmode[c] = (wf32[c] > 480) ? 1 : 0;
            imode[c] = (!idl[c]) ? 2 : ((!idu[c]) ? 1 : ((!idf[c]) ? 3 : 0));
        }
        int ic = -1;
        if (imode[0] && wmode[1]) ic = 0;
        else if (imode[1] && wmode[0]) ic = 1;
        g_bindfail = (ic < 0) ? 1 : 0;
        idsc = (ic < 0) ? 0 : ic;
        idsmode = imode[idsc] ? imode[idsc] : 1;
    }
    __syncthreads();

    const unsigned* idsbuf = idsc ? cB : cA;
    const unsigned* twbuf  = idsc ? cA : cB;
    int im = idsmode;
    for (int p = tid; p < NP; p += 256) {
        int id;
        if (im == 2)      id = (int)idsbuf[2 * p];
        else if (im == 3) id = (int)__uint_as_float(idsbuf[p]);
        else              id = (int)idsbuf[p];
        g_ids[p] = id & (NEXP - 1);
        g_tw[p] = __uint_as_float(twbuf[p]);
    }
    __syncthreads();

    for (int p = tid; p < NP; p += 256) atomicAdd(&cnt[g_ids[p]], 1);
    __syncthreads();
    if (tid == 0) {
        int a = 0;
        for (int e = 0; e < NEXP; e++) { g_off[e] = a; a += cnt[e]; }
        g_off[NEXP] = a;
    }
    __syncthreads();
    if (tid < NEXP) cur[tid] = g_off[tid];
    __syncthreads();
    for (int p = tid; p < NP; p += 256) {
        int pos = atomicAdd(&cur[g_ids[p]], 1);
        g_pairs[pos & (NP - 1)] = p;
    }
    __syncthreads();
    if (tid == 0) g_setupdone = 1;
}

// -------- seeds: zero out (down-GEMM accumulates into it) + sentinels --------
__global__ __launch_bounds__(256) void seed_kernel(float* __restrict__ outv) {
    int i = blockIdx.x * blockDim.x + threadIdx.x;
    if (i == 0) { g_t[0] = 777.0f; g_t2[0] = 777.0f; }
    if (i < 256) g_up[i] = 12345.0f;
    if (i < NTOK * DDIM) outv[i] = 0.0f;
}

// -------- LoRA-A GEMV (fp32) --------
template <bool DOWN>
__global__ __launch_bounds__(256) void lora_t_kernel(const float* __restrict__ Xv,
                                                     const float* __restrict__ A, int Dlen) {
    int p = blockIdx.x;
    int e = g_ids[p];
    float* T = DOWN ? g_t2 : g_t;
    int warp = threadIdx.x >> 5, lane = threadIdx.x & 31;
    const float* xrow = DOWN ? (g_act + (size_t)p * Dlen)
                             : (Xv + (size_t)(p >> 1) * Dlen);
    for (int r = warp; r < RDIM; r += 8) {
        const float* a = A + ((size_t)e * RDIM + r) * Dlen;
        float s = 0.f;
        for (int i = lane * 4; i < Dlen; i += 128) {
            float4 xv = *(const float4*)(xrow + i);
            float4 av = *(const float4*)(a + i);
            s += xv.x * av.x + xv.y * av.y + xv.z * av.z + xv.w * av.w;
        }
        #pragma unroll
        for (int o = 16; o; o >>= 1) s += __shfl_xor_sync(0xffffffffu, s, o);
        if (lane == 0) T[p * RDIM + r] = s;
    }
}

// ====== expert-grouped fp16 mma GEMM: 128x128x32, 3-stage cp.async, XOR swizzle ======
// 8 warps = 2(M) x 4(N), warp tile 64x32, mma m16n8k16.f16 (eps 2^-11 == tf32).
// Smem holds raw fp32; fragment loads are LDS.64 of adjacent (k,k+1) + cvt.rn.f16x2.
#define BM 128
#define BN 128
#define BK 32
#define STW (128 * 32)
#define PIPE_SMEM (3 * STW * 4 * 2 + 512)

__device__ __forceinline__ void stsw(unsigned* tile, int r, int kb, float4 v) {
    // stores raw fp32 bits (used only for the LoRA chunk)
    int idx = r * 32 + ((((kb >> 2) ^ (r & 7)) << 2));
    *(float4*)&tile[idx] = v;
}
__device__ __forceinline__ unsigned ldf16x2(const unsigned* tile, int r, int k) {
    // k even; loads (k, k+1) as float2 and packs to f16x2 (lo = k, hi = k+1)
    int off = r * 32 + (((k >> 2) ^ (r & 7)) << 2) + (k & 3);
    float2 v = *(const float2*)&tile[off];
    unsigned d;
    asm("cvt.rn.f16x2.f32 %0, %1, %2;" : "=r"(d) : "f"(v.y), "f"(v.x));
    return d;
}
__device__ __forceinline__ void cp16(uint32_t dst, const float* src) {
    asm volatile("cp.async.cg.shared.global [%0], [%1], 16;" :: "r"(dst), "l"(src));
}
__device__ __forceinline__ void issue_chunk(uint32_t a_s, uint32_t b_s,
                                            const float* ap, const float* bp,
                                            int lrow, int khalf) {
    int rx = (lrow & 7);
    #pragma unroll
    for (int j = 0; j < 4; j++) {
        int kc = (khalf >> 2) + j;
        uint32_t off = (uint32_t)(lrow * 32 + ((kc ^ rx) << 2)) * 4u;
        cp16(a_s + off, ap + j * 4);
        cp16(b_s + off, bp + j * 4);
    }
}
// fp16 MMA sweep over nks k16-groups; warp tile 64x32 (mt=4, nt=4)
__device__ __forceinline__ void frag_mma(const unsigned* As, const unsigned* Bs,
                                         int am_base, int bn_base, int kl2, int rquad,
                                         int nks, float c[4][4][4]) {
    for (int ks = 0; ks < nks; ks++) {
        int k0 = ks * 16 + kl2;
        unsigned a0[4], a1[4], a2[4], a3[4];
        #pragma unroll
        for (int mt = 0; mt < 4; mt++) {
            int r0 = am_base + mt * 16 + rquad;
            a0[mt] = ldf16x2(As, r0, k0);
            a1[mt] = ldf16x2(As, r0 + 8, k0);
            a2[mt] = ldf16x2(As, r0, k0 + 8);
            a3[mt] = ldf16x2(As, r0 + 8, k0 + 8);
        }
        #pragma unroll
        for (int nt = 0; nt < 4; nt++) {
            int cn = bn_base + nt * 8 + rquad;
            unsigned b0 = ldf16x2(Bs, cn, k0);
            unsigned b1 = ldf16x2(Bs, cn, k0 + 8);
            #pragma unroll
            for (int mt = 0; mt < 4; mt++) {
                asm volatile(
                    "mma.sync.aligned.m16n8k16.row.col.f32.f16.f16.f32 "
                    "{%0,%1,%2,%3}, {%4,%5,%6,%7}, {%8,%9}, {%0,%1,%2,%3};"
                    : "+f"(c[mt][nt][0]), "+f"(c[mt][nt][1]),
                      "+f"(c[mt][nt][2]), "+f"(c[mt][nt][3])
                    : "r"(a0[mt]), "r"(a1[mt]), "r"(a2[mt]), "r"(a3[mt]),
                      "r"(b0), "r"(b1));
            }
        }
    }
}

template <bool IS_DOWN>
__global__ __launch_bounds__(256, 2) void mma_gemm(const float* __restrict__ Av,   // hidden (up only)
                                                   const float* __restrict__ W,    // [E, Ncols, Kd]
                                                   const float* __restrict__ LB,   // [E, Ncols, R]
                                                   float* __restrict__ outv,       // out (down only)
                                                   int Kd, int Ncols) {
    int e = blockIdx.z;
    int mstart = g_off[e] + blockIdx.y * BM;
    int mend = g_off[e + 1];
    if (mstart >= mend) return;
    int mv = min(BM, mend - mstart);
    int o0 = blockIdx.x * BN;

    extern __shared__ __align__(16) unsigned dynsmem[];
    unsigned* Abuf = dynsmem;                    // 3 stages x 4096 words
    unsigned* Bbuf = dynsmem + 3 * STW;
    int* Pr = (int*)(dynsmem + 6 * STW);

    int tid = threadIdx.x;
    int lane = tid & 31, wid = tid >> 5;
    int am_base = (wid >> 2) * 64;
    int bn_base = (wid & 3) * 32;

    if (tid < BM) Pr[tid] = g_pairs[mstart + ((tid < mv) ? tid : (mv - 1))];
    __syncthreads();

    int lrow  = tid >> 1;            // 0..127
    int khalf = (tid & 1) * 16;      // 0 or 16

    int prow = Pr[lrow];
    int arow = IS_DOWN ? prow : (prow >> 1);
    const float* abase = (IS_DOWN ? g_act : Av) + (size_t)arow * Kd + khalf;
    const float* bbase = W + ((size_t)e * Ncols + o0 + lrow) * Kd + khalf;

    uint32_t a_s0 = smem_u32(Abuf), b_s0 = smem_u32(Bbuf);

    float c[4][4][4];
    #pragma unroll
    for (int i = 0; i < 4; i++)
        #pragma unroll
        for (int j = 0; j < 4; j++)
            #pragma unroll
            for (int q = 0; q < 4; q++) c[i][j][q] = 0.f;

    int nch = Kd / BK;
    int kl2 = (lane & 3) * 2;
    int rquad = lane >> 2;

    // prologue: stage chunks 0,1
    issue_chunk(a_s0, b_s0, abase, bbase, lrow, khalf);
    CP_COMMIT();
    if (nch > 1) issue_chunk(a_s0 + STW * 4, b_s0 + STW * 4, abase + BK, bbase + BK, lrow, khalf);
    CP_COMMIT();

    for (int ch = 0; ch < nch; ch++) {
        CP_WAIT1();
        __syncthreads();
        int nx = ch + 2;
        if (nx < nch) {
            int st = nx - (nx / 3) * 3;
            issue_chunk(a_s0 + st * STW * 4, b_s0 + st * STW * 4,
                        abase + nx * BK, bbase + nx * BK, lrow, khalf);
        }
        CP_COMMIT();
        int st = ch - (ch / 3) * 3;
        frag_mma(Abuf + st * STW, Bbuf + st * STW, am_base, bn_base, kl2, rquad, 2, c);
    }

    // ---- LoRA-B extension chunk (K=16): A <- SCALE*T[p][r], B <- LB[n][r] ----
    CP_WAIT0();
    __syncthreads();
    if ((tid & 1) == 0) {
        int row = tid >> 1;
        const float* tp = (IS_DOWN ? g_t2 : g_t) + Pr[row] * RDIM;
        const float* lp = LB + ((size_t)e * Ncols + o0 + row) * RDIM;
        #pragma unroll
        for (int j = 0; j < 4; j++) {
            float4 v = *(const float4*)(tp + j * 4);
            v.x *= SCALE; v.y *= SCALE; v.z *= SCALE; v.w *= SCALE;
            stsw(Abuf, row, j * 4, v);
            stsw(Bbuf, row, j * 4, *(const float4*)(lp + j * 4));
        }
    }
    __syncthreads();
    frag_mma(Abuf, Bbuf, am_base, bn_base, kl2, rquad, 1, c);

    // ---- writeout: up -> g_up; down -> atomicAdd into out (k-sum fused) ----
    #pragma unroll
    for (int mt = 0; mt < 4; mt++) {
        int m0 = am_base + mt * 16 + rquad;
        #pragma unroll
        for (int half = 0; half < 2; half++) {
            int m = m0 + half * 8;
            if (m >= mv) continue;
            int p = Pr[m];
            if (IS_DOWN) {
                float w = g_tw[p];
                float* op = outv + (size_t)(p >> 1) * Ncols + o0;
                #pragma unroll
                for (int nt = 0; nt < 4; nt++) {
                    int n = bn_base + nt * 8 + (lane & 3) * 2;
                    atomicAdd(&op[n],     c[mt][nt][half * 2 + 0] * w);
                    atomicAdd(&op[n + 1], c[mt][nt][half * 2 + 1] * w);
                }
            } else {
                float* op = g_up + (size_t)p * Ncols + o0;
                #pragma unroll
                for (int nt = 0; nt < 4; nt++) {
                    int n = bn_base + nt * 8 + (lane & 3) * 2;
                    float2 v;
                    v.x = c[mt][nt][half * 2 + 0];
                    v.y = c[mt][nt][half * 2 + 1];
                    *(float2*)&op[n] = v;
                }
            }
        }
    }
}

// -------- gelu(up[:H]) * up[H:] --------
__global__ __launch_bounds__(256) void act_kernel() {
    int i = blockIdx.x * blockDim.x + threadIdx.x;
    if (i >= NP * HDIM) return;
    int p = i >> 10, h = i & (HDIM - 1);
    float a = g_up[(size_t)p * UPW + h];
    float b = g_up[(size_t)p * UPW + HDIM + h];
    float ge = 0.5f * a * (1.0f + erff(a * 0.70710678118654752f));
    g_act[(size_t)p * HDIM + h] = ge * b;
}

// -------- verdict: failure-only overwrite (healthy path leaves out untouched) --------
__global__ __launch_bounds__(256) void verdict_kernel(float* __restrict__ outv) {
    int code = 0;
    if (!g_setupdone)               code = 1;
    else if (g_bindfail)            code = 2;
    else if (g_off[NEXP] != NP)     code = 4;
    else if (g_t[0] == 777.0f)      code = 3;
    else if (g_up[0] == 12345.0f)   code = 8;
    else if (g_t2[0] == 777.0f)     code = 5;
    if (code == 0) return;
    for (int i = blockIdx.x * blockDim.x + threadIdx.x; i < NTOK * DDIM; i += 65536)
        outv[i] = (float)code;
}

extern "C" void kernel_launch(void* const* d_in, const int* in_sizes, int n_in,
                              void* d_out, int out_size) {
    long long mx = 0;
    for (int i = 0; i < n_in; i++) if ((long long)in_sizes[i] > mx) mx = in_sizes[i];
    int div = 1;
    if (mx == 268435456LL) div = 4;
    else if (mx == 134217728LL) div = 2;

    int idx_hidden = -1, idx_wup = -1, idx_wdown = -1, idx_downa = -1;
    int idxc[2] = {-1, -1}; int nc = 0;
    int idx512k[3] = {-1, -1, -1}; int n512k = 0;
    for (int i = 0; i < n_in; i++) {
        long long es = (long long)in_sizes[i] / div;
        if      (es == 2097152)  idx_hidden = i;
        else if (es == 67108864) idx_wup = i;
        else if (es == 33554432) idx_wdown = i;
        else if (es == 262144)   idx_downa = i;
        else if (es == 2048 || (div == 2 && es == 4096)) { if (nc < 2) idxc[nc++] = i; }
        else if (es == 524288)   { if (n512k < 3) idx512k[n512k++] = i; }
    }

    int idx_upa = -1, idx_upb = -1, idx_downb = -1;
    bool ok = (idx_hidden >= 0 && idx_wup >= 0 && idx_wdown >= 0 && idx_downa >= 0 &&
               nc == 2 && n512k == 3);
    if (ok) {
        if (idx_downa < idx512k[0]) { idx_downb = idx512k[0]; idx_upa = idx512k[1]; idx_upb = idx512k[2]; }
        else                        { idx_upa = idx512k[0]; idx_upb = idx512k[1]; idx_downb = idx512k[2]; }
    } else if (n_in >= 9) {
        idx_hidden = 0; idxc[0] = 1; idxc[1] = 2; idx_wup = 3; idx_wdown = 4;
        idx_upa = 5; idx_upb = 6; idx_downa = 7; idx_downb = 8;
    } else {
        return;
    }

    const float* hidden = (const float*)d_in[idx_hidden];
    const float* w_up   = (const float*)d_in[idx_wup];
    const float* w_down = (const float*)d_in[idx_wdown];
    const float* up_a   = (const float*)d_in[idx_upa];
    const float* up_b   = (const float*)d_in[idx_upb];
    const float* down_a = (const float*)d_in[idx_downa];
    const float* down_b = (const float*)d_in[idx_downb];
    float* out = (float*)d_out;

    static int smem_set = 0;
    if (!smem_set) {
        cudaFuncSetAttribute(mma_gemm<false>, cudaFuncAttributeMaxDynamicSharedMemorySize, PIPE_SMEM);
        cudaFuncSetAttribute(mma_gemm<true>,  cudaFuncAttributeMaxDynamicSharedMemorySize, PIPE_SMEM);
        smem_set = 1;
    }

    setup_kernel<<<1, 256>>>((const unsigned*)d_in[idxc[0]], (const unsigned*)d_in[idxc[1]]);
    seed_kernel<<<(NTOK * DDIM + 255) / 256, 256>>>(out);

    lora_t_kernel<false><<<NP, 256>>>(hidden, up_a, DDIM);

    {
        dim3 grid(UPW / BN, (NP + BM - 1) / BM, NEXP);
        mma_gemm<false><<<grid, 256, PIPE_SMEM>>>(hidden, w_up, up_b, nullptr, DDIM, UPW);
    }

    act_kernel<<<(NP * HDIM + 255) / 256, 256>>>();

    lora_t_kernel<true><<<NP, 256>>>(nullptr, down_a, HDIM);

    {
        dim3 grid(DDIM / BN, (NP + BM - 1) / BM, NEXP);
        mma_gemm<true><<<grid, 256, PIPE_SMEM>>>(nullptr, w_down, down_b, out, HDIM, DDIM);
    }

    verdict_kernel<<<256, 256>>>(out);
}